// round 12
// baseline (speedup 1.0000x reference)
#include <cuda_runtime.h>

#define EPS   1e-3f
#define C0    32
#define C1    32
#define CIN   16
#define MAX_NODES 65536

// ---- folded parameters (written by prep_kernel) ----
__device__ __align__(16) float g_wpos[3 * C0];      // w_pos * s0 (per out-channel)
__device__ __align__(16) float g_wfeat[CIN * C0];   // w_feat * sf
__device__ __align__(16) float g_biasn[C0];         // bias0 + biasf (into node precompute)
__device__ __align__(16) float g_w1[C0 * C1];       // w1 * s1
__device__ __align__(16) float g_b1[C1];            // b1*s1 + bn1_b - bn1_m*s1
// ---- node-level precomputed features: BNf(ref_feat @ w_feat) + bias0 ----
__device__ __align__(16) float g_node[(size_t)MAX_NODES * C0];

// Fold all BatchNorms into the linear layers. One warp, one launch.
__global__ void prep_kernel(
    const float* __restrict__ wpos,
    const float* __restrict__ g0, const float* __restrict__ b0,
    const float* __restrict__ m0, const float* __restrict__ v0,
    const float* __restrict__ wfeat,
    const float* __restrict__ gf, const float* __restrict__ bf,
    const float* __restrict__ mf, const float* __restrict__ vf,
    const float* __restrict__ w1, const float* __restrict__ b1,
    const float* __restrict__ g1, const float* __restrict__ b1b,
    const float* __restrict__ m1, const float* __restrict__ v1)
{
    int c = threadIdx.x;
    if (c >= C0) return;

    float s0    = g0[c] * rsqrtf(v0[c] + EPS);
    float bias0 = b0[c] - m0[c] * s0;
#pragma unroll
    for (int k = 0; k < 3; k++) g_wpos[k * C0 + c] = wpos[k * C0 + c] * s0;

    float sf    = gf[c] * rsqrtf(vf[c] + EPS);
    float biasf = bf[c] - mf[c] * sf;
#pragma unroll
    for (int k = 0; k < CIN; k++) g_wfeat[k * C0 + c] = wfeat[k * C0 + c] * sf;

    g_biasn[c] = bias0 + biasf;

    float s1 = g1[c] * rsqrtf(v1[c] + EPS);
#pragma unroll
    for (int k = 0; k < C0; k++) g_w1[k * C1 + c] = w1[k * C1 + c] * s1;
    g_b1[c] = b1[c] * s1 + b1b[c] - m1[c] * s1;
}

// Per-node feature projection: g_node[n] = ref_feat[n] @ g_wfeat + g_biasn
__global__ void node_kernel(const float* __restrict__ ref_feat, int n_ref)
{
    __shared__ __align__(16) float sw[CIN * C0];
    __shared__ __align__(16) float sb[C0];
    for (int i = threadIdx.x; i < CIN * C0; i += blockDim.x) sw[i] = g_wfeat[i];
    if (threadIdx.x < C0) sb[threadIdx.x] = g_biasn[threadIdx.x];
    __syncthreads();

    int n = blockIdx.x * blockDim.x + threadIdx.x;
    if (n >= n_ref) return;

    float f[CIN];
    const float4* fp = reinterpret_cast<const float4*>(ref_feat + (size_t)n * CIN);
#pragma unroll
    for (int i = 0; i < CIN / 4; i++) {
        float4 t = __ldg(fp + i);
        f[4*i+0] = t.x; f[4*i+1] = t.y; f[4*i+2] = t.z; f[4*i+3] = t.w;
    }

    float4* outp = reinterpret_cast<float4*>(g_node + (size_t)n * C0);
#pragma unroll
    for (int c4 = 0; c4 < C0 / 4; c4++) {
        float4 acc = *reinterpret_cast<const float4*>(&sb[c4 * 4]);
#pragma unroll
        for (int k = 0; k < CIN; k++) {
            float4 w = *reinterpret_cast<const float4*>(&sw[k * C0 + c4 * 4]);
            acc.x = fmaf(f[k], w.x, acc.x);
            acc.y = fmaf(f[k], w.y, acc.y);
            acc.z = fmaf(f[k], w.z, acc.z);
            acc.w = fmaf(f[k], w.w, acc.w);
        }
        outp[c4] = acc;
    }
}

__global__ void zero_kernel(float* __restrict__ out, int n)
{
    int i = blockIdx.x * blockDim.x + threadIdx.x;
    if (i < n) out[i] = 0.0f;
}

// Per-edge: h = relu(pos_diff @ w_pos' + node[r]); o = relu(h @ w1' + b1');
// scatter-max into out[q]. Read-check before atomic to collapse atomic traffic.
__global__ void __launch_bounds__(256) edge_kernel(
    const float* __restrict__ ref_bxyz,
    const float* __restrict__ query_bxyz,
    const int*   __restrict__ e_ref,
    const int*   __restrict__ e_query,
    float*       __restrict__ out,
    int E)
{
    __shared__ __align__(16) float sw1[C0 * C1];
    __shared__ __align__(16) float swp[3 * C0];
    __shared__ __align__(16) float sb1[C1];
    for (int i = threadIdx.x; i < C0 * C1; i += blockDim.x) sw1[i] = g_w1[i];
    for (int i = threadIdx.x; i < 3 * C0;  i += blockDim.x) swp[i] = g_wpos[i];
    if (threadIdx.x < C1) sb1[threadIdx.x] = g_b1[threadIdx.x];
    __syncthreads();

    for (int e = blockIdx.x * blockDim.x + threadIdx.x; e < E;
         e += gridDim.x * blockDim.x)
    {
        int r = e_ref[e];
        int q = e_query[e];

        float4 rb = __ldg(reinterpret_cast<const float4*>(ref_bxyz)   + r);
        float4 qb = __ldg(reinterpret_cast<const float4*>(query_bxyz) + q);
        // columns 1..3 of bxyz
        float dx = rb.y - qb.y;
        float dy = rb.z - qb.z;
        float dz = rb.w - qb.w;

        // layer 0: h[c] = relu(pos_diff @ w_pos' + node[r][c])  (biases folded into node)
        float h[C0];
        const float4* np = reinterpret_cast<const float4*>(g_node + (size_t)r * C0);
#pragma unroll
        for (int c4 = 0; c4 < C0 / 4; c4++) {
            float4 nb = __ldg(np + c4);
            float nbv[4] = {nb.x, nb.y, nb.z, nb.w};
#pragma unroll
            for (int j = 0; j < 4; j++) {
                int c = c4 * 4 + j;
                float v = fmaf(dx, swp[c],
                          fmaf(dy, swp[C0 + c],
                          fmaf(dz, swp[2 * C0 + c], nbv[j])));
                h[c] = fmaxf(v, 0.0f);
            }
        }

        // layer 1 + relu + scatter-max
        float*       outq  = out + (size_t)q * C1;
        int*         outqi = reinterpret_cast<int*>(outq);
        const float4* curp = reinterpret_cast<const float4*>(outq);
#pragma unroll
        for (int c4 = 0; c4 < C1 / 4; c4++) {
            float4 acc = *reinterpret_cast<const float4*>(&sb1[c4 * 4]);
#pragma unroll
            for (int k = 0; k < C0; k++) {
                float4 w = *reinterpret_cast<const float4*>(&sw1[k * C1 + c4 * 4]);
                acc.x = fmaf(h[k], w.x, acc.x);
                acc.y = fmaf(h[k], w.y, acc.y);
                acc.z = fmaf(h[k], w.z, acc.z);
                acc.w = fmaf(h[k], w.w, acc.w);
            }
            float vals[4] = { fmaxf(acc.x, 0.0f), fmaxf(acc.y, 0.0f),
                              fmaxf(acc.z, 0.0f), fmaxf(acc.w, 0.0f) };

            // peek current maxima via L2 (atomics update L2; __ldcg is coherent there)
            float4 cur = __ldcg(curp + c4);
            float curv[4] = {cur.x, cur.y, cur.z, cur.w};
#pragma unroll
            for (int j = 0; j < 4; j++) {
                if (vals[j] > curv[j]) {
                    // values are >= 0 post-ReLU: int-bit atomicMax is order-correct
                    atomicMax(&outqi[c4 * 4 + j], __float_as_int(vals[j]));
                }
            }
        }
    }
}

extern "C" void kernel_launch(void* const* d_in, const int* in_sizes, int n_in,
                              void* d_out, int out_size)
{
    const float* ref_bxyz   = (const float*)d_in[0];
    const float* ref_feat   = (const float*)d_in[1];
    const float* query_bxyz = (const float*)d_in[2];
    const int*   e_ref      = (const int*)d_in[3];
    const int*   e_query    = (const int*)d_in[4];
    const float* w_pos      = (const float*)d_in[5];
    const float* bn0_g      = (const float*)d_in[6];
    const float* bn0_b      = (const float*)d_in[7];
    const float* bn0_m      = (const float*)d_in[8];
    const float* bn0_v      = (const float*)d_in[9];
    const float* w_feat     = (const float*)d_in[10];
    const float* bnf_g      = (const float*)d_in[11];
    const float* bnf_b      = (const float*)d_in[12];
    const float* bnf_m      = (const float*)d_in[13];
    const float* bnf_v      = (const float*)d_in[14];
    const float* w1         = (const float*)d_in[15];
    const float* b1         = (const float*)d_in[16];
    const float* bn1_g      = (const float*)d_in[17];
    const float* bn1_b      = (const float*)d_in[18];
    const float* bn1_m      = (const float*)d_in[19];
    const float* bn1_v      = (const float*)d_in[20];

    float* out = (float*)d_out;

    int n_ref = in_sizes[0] / 4;
    int E     = in_sizes[3];

    prep_kernel<<<1, 32>>>(w_pos, bn0_g, bn0_b, bn0_m, bn0_v,
                           w_feat, bnf_g, bnf_b, bnf_m, bnf_v,
                           w1, b1, bn1_g, bn1_b, bn1_m, bn1_v);

    node_kernel<<<(n_ref + 255) / 256, 256>>>(ref_feat, n_ref);

    zero_kernel<<<(out_size + 255) / 256, 256>>>(out, out_size);

    int blocks = (E + 255) / 256;
    if (blocks > 65535) blocks = 65535;
    edge_kernel<<<blocks, 256>>>(ref_bxyz, query_bxyz, e_ref, e_query, out, E);
}

// round 13
// speedup vs baseline: 1.0444x; 1.0444x over previous
#include <cuda_runtime.h>

#define EPS   1e-3f
#define C0    32
#define C1    32
#define CIN   16
#define MAX_NODES 65536

// ---- folded parameters (written by prep_kernel) ----
__device__ __align__(16) float g_wpos[3 * C0];      // w_pos * s0
__device__ __align__(16) float g_wfeat[CIN * C0];   // w_feat * sf
__device__ __align__(16) float g_biasn[C0];         // bias0 + biasf
__device__ __align__(16) float g_w1t[C0 * C1];      // TRANSPOSED: [c][k] = w1[k][c]*s1(c)
__device__ __align__(16) float g_b1[C1];            // b1*s1 + bn1_b - bn1_m*s1
// ---- node-level precomputed features ----
__device__ __align__(16) float g_node[(size_t)MAX_NODES * C0];

// Fold all BatchNorms into the linear layers. One warp, one launch.
__global__ void prep_kernel(
    const float* __restrict__ wpos,
    const float* __restrict__ g0, const float* __restrict__ b0,
    const float* __restrict__ m0, const float* __restrict__ v0,
    const float* __restrict__ wfeat,
    const float* __restrict__ gf, const float* __restrict__ bf,
    const float* __restrict__ mf, const float* __restrict__ vf,
    const float* __restrict__ w1, const float* __restrict__ b1,
    const float* __restrict__ g1, const float* __restrict__ b1b,
    const float* __restrict__ m1, const float* __restrict__ v1)
{
    int c = threadIdx.x;
    if (c >= C0) return;

    float s0    = g0[c] * rsqrtf(v0[c] + EPS);
    float bias0 = b0[c] - m0[c] * s0;
#pragma unroll
    for (int k = 0; k < 3; k++) g_wpos[k * C0 + c] = wpos[k * C0 + c] * s0;

    float sf    = gf[c] * rsqrtf(vf[c] + EPS);
    float biasf = bf[c] - mf[c] * sf;
#pragma unroll
    for (int k = 0; k < CIN; k++) g_wfeat[k * C0 + c] = wfeat[k * C0 + c] * sf;

    g_biasn[c] = bias0 + biasf;

    float s1 = g1[c] * rsqrtf(v1[c] + EPS);
    // transposed, per-output-channel row: g_w1t[c][k] = w1[k][c] * s1(c)
#pragma unroll
    for (int k = 0; k < C0; k++) g_w1t[c * C0 + k] = w1[k * C1 + c] * s1;
    g_b1[c] = b1[c] * s1 + b1b[c] - m1[c] * s1;
}

// Per-node feature projection: g_node[n] = ref_feat[n] @ g_wfeat + g_biasn
__global__ void node_kernel(const float* __restrict__ ref_feat, int n_ref)
{
    __shared__ __align__(16) float sw[CIN * C0];
    __shared__ __align__(16) float sb[C0];
    for (int i = threadIdx.x; i < CIN * C0; i += blockDim.x) sw[i] = g_wfeat[i];
    if (threadIdx.x < C0) sb[threadIdx.x] = g_biasn[threadIdx.x];
    __syncthreads();

    int n = blockIdx.x * blockDim.x + threadIdx.x;
    if (n >= n_ref) return;

    float f[CIN];
    const float4* fp = reinterpret_cast<const float4*>(ref_feat + (size_t)n * CIN);
#pragma unroll
    for (int i = 0; i < CIN / 4; i++) {
        float4 t = __ldg(fp + i);
        f[4*i+0] = t.x; f[4*i+1] = t.y; f[4*i+2] = t.z; f[4*i+3] = t.w;
    }

    float4* outp = reinterpret_cast<float4*>(g_node + (size_t)n * C0);
#pragma unroll
    for (int c4 = 0; c4 < C0 / 4; c4++) {
        float4 acc = *reinterpret_cast<const float4*>(&sb[c4 * 4]);
#pragma unroll
        for (int k = 0; k < CIN; k++) {
            float4 w = *reinterpret_cast<const float4*>(&sw[k * C0 + c4 * 4]);
            acc.x = fmaf(f[k], w.x, acc.x);
            acc.y = fmaf(f[k], w.y, acc.y);
            acc.z = fmaf(f[k], w.z, acc.z);
            acc.w = fmaf(f[k], w.w, acc.w);
        }
        outp[c4] = acc;
    }
}

__global__ void zero_kernel(float* __restrict__ out, int n)
{
    int i = blockIdx.x * blockDim.x + threadIdx.x;
    if (i < n) out[i] = 0.0f;
}

// Warp-per-edge, lane = output channel. All gathers coalesced; layer-1 via
// packed fp32x2 FFMA with k-dimension packing (w1 column in registers).
__global__ void __launch_bounds__(256) edge_kernel(
    const float* __restrict__ ref_bxyz,
    const float* __restrict__ query_bxyz,
    const int*   __restrict__ e_ref,
    const int*   __restrict__ e_query,
    float*       __restrict__ out,
    int E)
{
    // per-warp double-buffered h: 2 x (32 floats + 16B pad) = 72 floats/warp
    __shared__ __align__(16) float sh[8 * 72];

    const int lane = threadIdx.x & 31;
    const int wid  = threadIdx.x >> 5;

    // per-lane (= per-channel) constants
    const float wp0 = g_wpos[lane];
    const float wp1 = g_wpos[C0 + lane];
    const float wp2 = g_wpos[2 * C0 + lane];
    const float b1c = g_b1[lane];

    // w1 column of this lane, interleaved as 16 packed f32x2 pairs over k
    unsigned long long w1c[16];
    {
        const unsigned long long* wt =
            reinterpret_cast<const unsigned long long*>(g_w1t + lane * C0);
#pragma unroll
        for (int j = 0; j < 16; j++) w1c[j] = __ldg(wt + j);
    }

    // shared-space address of this warp's h buffers
    unsigned int hbase;
    {
        const float* p = &sh[wid * 72];
        asm("{ .reg .u64 t; cvta.to.shared.u64 t, %1; cvt.u32.u64 %0, t; }"
            : "=r"(hbase) : "l"(p));
    }

    const float4* rbx = reinterpret_cast<const float4*>(ref_bxyz);
    const float4* qbx = reinterpret_cast<const float4*>(query_bxyz);
    int* outi = reinterpret_cast<int*>(out);

    const int nwarps = (gridDim.x * blockDim.x) >> 5;
    int e = (blockIdx.x * blockDim.x + threadIdx.x) >> 5;
    if (e >= E) return;

    // prefetched indices for current edge
    int r = __ldg(e_ref + e);
    int q = __ldg(e_query + e);
    unsigned int hoff = 0;

    while (true) {
        // issue all memory for this edge up front (one L2 latency window)
        float4 rb = __ldg(rbx + r);                        // warp-broadcast
        float4 qb = __ldg(qbx + q);                        // warp-broadcast
        float  nodev = __ldg(g_node + (size_t)r * C0 + lane);  // coalesced 128B
        float  peek  = __ldcg(out + (size_t)q * C1 + lane);    // coalesced 128B

        int enext = e + nwarps;
        int rn = 0, qn = 0;
        if (enext < E) {                                   // prefetch next indices
            rn = __ldg(e_ref + enext);
            qn = __ldg(e_query + enext);
        }

        float dx = rb.y - qb.y, dy = rb.z - qb.z, dz = rb.w - qb.w;
        float h = fmaf(dx, wp0, fmaf(dy, wp1, fmaf(dz, wp2, nodev)));
        h = fmaxf(h, 0.0f);

        unsigned int hb = hbase + hoff;
        asm volatile("st.shared.f32 [%0], %1;" :: "r"(hb + lane * 4), "f"(h));
        __syncwarp();

        // layer 1: acc2 = sum_k {h_k, h_k+1} * {w1[k][c], w1[k+1][c]}  (packed over k)
        unsigned long long acc = 0ull;   // {+0.0f, +0.0f}
#pragma unroll
        for (int j = 0; j < 8; j++) {
            unsigned long long p0, p1;
            asm volatile("ld.shared.v2.b64 {%0, %1}, [%2];"
                         : "=l"(p0), "=l"(p1) : "r"(hb + j * 16));
            asm("fma.rn.f32x2 %0, %1, %2, %3;"
                : "=l"(acc) : "l"(p0), "l"(w1c[2 * j]), "l"(acc));
            asm("fma.rn.f32x2 %0, %1, %2, %3;"
                : "=l"(acc) : "l"(p1), "l"(w1c[2 * j + 1]), "l"(acc));
        }
        float a0, a1;
        asm("mov.b64 {%0, %1}, %2;" : "=f"(a0), "=f"(a1) : "l"(acc));
        float v = fmaxf((a0 + a1) + b1c, 0.0f);

        // post-ReLU values are >= 0: int-bit atomicMax is order-correct.
        // Peek (L2-coherent) filters ~90% of atomics.
        if (v > peek)
            atomicMax(outi + (size_t)q * C1 + lane, __float_as_int(v));

        if (enext >= E) break;
        e = enext; r = rn; q = qn;
        hoff ^= 144;   // flip double buffer (36 floats * 4B)
    }
}

extern "C" void kernel_launch(void* const* d_in, const int* in_sizes, int n_in,
                              void* d_out, int out_size)
{
    const float* ref_bxyz   = (const float*)d_in[0];
    const float* ref_feat   = (const float*)d_in[1];
    const float* query_bxyz = (const float*)d_in[2];
    const int*   e_ref      = (const int*)d_in[3];
    const int*   e_query    = (const int*)d_in[4];
    const float* w_pos      = (const float*)d_in[5];
    const float* bn0_g      = (const float*)d_in[6];
    const float* bn0_b      = (const float*)d_in[7];
    const float* bn0_m      = (const float*)d_in[8];
    const float* bn0_v      = (const float*)d_in[9];
    const float* w_feat     = (const float*)d_in[10];
    const float* bnf_g      = (const float*)d_in[11];
    const float* bnf_b      = (const float*)d_in[12];
    const float* bnf_m      = (const float*)d_in[13];
    const float* bnf_v      = (const float*)d_in[14];
    const float* w1         = (const float*)d_in[15];
    const float* b1         = (const float*)d_in[16];
    const float* bn1_g      = (const float*)d_in[17];
    const float* bn1_b      = (const float*)d_in[18];
    const float* bn1_m      = (const float*)d_in[19];
    const float* bn1_v      = (const float*)d_in[20];

    float* out = (float*)d_out;

    int n_ref = in_sizes[0] / 4;
    int E     = in_sizes[3];

    prep_kernel<<<1, 32>>>(w_pos, bn0_g, bn0_b, bn0_m, bn0_v,
                           w_feat, bnf_g, bnf_b, bnf_m, bnf_v,
                           w1, b1, bn1_g, bn1_b, bn1_m, bn1_v);

    node_kernel<<<(n_ref + 255) / 256, 256>>>(ref_feat, n_ref);

    zero_kernel<<<(out_size + 255) / 256, 256>>>(out, out_size);

    edge_kernel<<<888, 256>>>(ref_bxyz, query_bxyz, e_ref, e_query, out, E);
}